// round 1
// baseline (speedup 1.0000x reference)
#include <cuda_runtime.h>
#include <math.h>

#define BATCH 2
#define C 256
#define HH 256
#define WW 256
#define HW 65536
#define NH 16
#define DH 16

// Scratch (device globals — no allocation allowed)
__device__ float g_qkv[(size_t)BATCH * 3 * C * HW]; // 402 MB
__device__ float g_o  [(size_t)BATCH * C * HW];     // 134 MB
__device__ float g_xy [(size_t)BATCH * C * HW];     // 134 MB
__device__ float g_bn [(size_t)BATCH * C * HW];     // 134 MB

// ---------------------------------------------------------------------------
// Generic 1x1-conv GEMM:  Y[b][m][p] = sum_k Wm[m][k] * X[b][k][p],  K = C
// Tiles: 64(M) x 64(N) x 16(K), 256 threads, 4x4 micro-tile per thread.
// ---------------------------------------------------------------------------
__global__ __launch_bounds__(256) void k_gemm1x1(
    const float* __restrict__ Wm, const float* __restrict__ X,
    float* __restrict__ Y, int OC) {
  __shared__ float As[16][64];
  __shared__ float Bs[16][68];
  const int b = blockIdx.z;
  const float* Xb = X + (size_t)b * C * HW;
  float* Yb = Y + (size_t)b * OC * HW;
  const int m0 = blockIdx.x * 64;
  const int p0 = blockIdx.y * 64;
  const int tid = threadIdx.x;
  const int tx = tid & 15, ty = tid >> 4;
  const int am = tid >> 2, ak4 = (tid & 3) * 4;
  const int bk = tid >> 4, bn4 = (tid & 15) * 4;
  float acc[4][4] = {};
  for (int k0 = 0; k0 < C; k0 += 16) {
    float4 a = *(const float4*)&Wm[(m0 + am) * C + k0 + ak4];
    As[ak4 + 0][am] = a.x; As[ak4 + 1][am] = a.y;
    As[ak4 + 2][am] = a.z; As[ak4 + 3][am] = a.w;
    *(float4*)&Bs[bk][bn4] = *(const float4*)&Xb[(k0 + bk) * HW + p0 + bn4];
    __syncthreads();
#pragma unroll
    for (int k = 0; k < 16; k++) {
      float4 av = *(const float4*)&As[k][ty * 4];
      float4 bv = *(const float4*)&Bs[k][tx * 4];
      float aa[4] = {av.x, av.y, av.z, av.w};
      float bb[4] = {bv.x, bv.y, bv.z, bv.w};
#pragma unroll
      for (int i = 0; i < 4; i++)
#pragma unroll
        for (int j = 0; j < 4; j++) acc[i][j] += aa[i] * bb[j];
    }
    __syncthreads();
  }
#pragma unroll
  for (int i = 0; i < 4; i++) {
    const int m = m0 + ty * 4 + i;
#pragma unroll
    for (int j = 0; j < 4; j++)
      Yb[m * HW + p0 + tx * 4 + j] = acc[i][j];
  }
}

// ---------------------------------------------------------------------------
// Window attention: one block per (window, head), 64 threads = 64 tokens.
// ---------------------------------------------------------------------------
__global__ __launch_bounds__(64) void k_attn(
    const float* __restrict__ qkv, const float* __restrict__ rel_table,
    float* __restrict__ o) {
  const int n = blockIdx.x;   // window 0..2047
  const int h = blockIdx.y;   // head
  const int i = threadIdx.x;  // token
  __shared__ float ks[64][17];
  __shared__ float vs[64][17];
  __shared__ float rt[225];
  const int b = n >> 10;
  const int rem = n & 1023;
  const int hh = rem >> 5, ww = rem & 31;
  const int yy = i >> 3, xx = i & 7;
  const int py = hh * 8 + yy, px = ww * 8 + xx;
  const size_t base = ((size_t)b * 3 * C + h * DH) * HW + py * 256 + px;
  const float scale = 0.25f;  // d^-0.5, d = 16
  float q[16];
#pragma unroll
  for (int dc = 0; dc < 16; dc++) q[dc] = qkv[base + (size_t)dc * HW] * scale;
#pragma unroll
  for (int dc = 0; dc < 16; dc++) ks[i][dc] = qkv[base + (size_t)(C + dc) * HW];
#pragma unroll
  for (int dc = 0; dc < 16; dc++) vs[i][dc] = qkv[base + (size_t)(2 * C + dc) * HW];
  for (int t = i; t < 225; t += 64) rt[t] = rel_table[t * NH + h];
  __syncthreads();

  float p[64];
  float mx = -1e30f;
#pragma unroll
  for (int j = 0; j < 64; j++) {
    const int yj = j >> 3, xj = j & 7;
    float s = 0.f;
#pragma unroll
    for (int dc = 0; dc < 16; dc++) s += q[dc] * ks[j][dc];
    s += rt[(yy - yj + 7) * 15 + (xx - xj + 7)];
    p[j] = s;
    mx = fmaxf(mx, s);
  }
  float sum = 0.f;
#pragma unroll
  for (int j = 0; j < 64; j++) { p[j] = __expf(p[j] - mx); sum += p[j]; }
  const float inv = 1.f / sum;
  const size_t obase = ((size_t)b * C + h * DH) * HW + py * 256 + px;
#pragma unroll
  for (int dc = 0; dc < 16; dc++) {
    float a = 0.f;
#pragma unroll
    for (int j = 0; j < 64; j++) a += p[j] * vs[j][dc];
    o[obase + (size_t)dc * HW] = a * inv;
  }
}

// ---------------------------------------------------------------------------
// 8-tap line conv as implicit-im2col GEMM, K = C*8 = 2048.
// A = weights [256][2048] (O, c*8+t) — contiguous for both w_attnx and w_attny.
// B[(c,t)][p] = In[c] shifted by t (rows if vertical, cols otherwise), with
// reflect-appended index 256 -> 254 and zero outside [0,256].
// ---------------------------------------------------------------------------
__global__ __launch_bounds__(256) void k_convline(
    const float* __restrict__ Wm, const float* __restrict__ bias,
    const float* __restrict__ In, float* __restrict__ Y,
    int vertical, int accumulate) {
  __shared__ float As[16][64];
  __shared__ float Bs[16][68];
  const int b = blockIdx.z;
  const float* Inb = In + (size_t)b * C * HW;
  float* Yb = Y + (size_t)b * C * HW;
  const int m0 = blockIdx.x * 64;
  const int p0 = blockIdx.y * 64;    // 64 pixels, always within one image row
  const int y = p0 >> 8;
  const int x0 = p0 & 255;
  const int tid = threadIdx.x;
  const int tx = tid & 15, ty = tid >> 4;
  const int am = tid >> 2, ak4 = (tid & 3) * 4;
  const int bk = tid >> 4, bn4 = (tid & 15) * 4;
  float acc[4][4] = {};
  for (int k0 = 0; k0 < 2048; k0 += 16) {
    float4 a = *(const float4*)&Wm[(m0 + am) * 2048 + k0 + ak4];
    As[ak4 + 0][am] = a.x; As[ak4 + 1][am] = a.y;
    As[ak4 + 2][am] = a.z; As[ak4 + 3][am] = a.w;
    {
      const int kg = k0 + bk;
      const int c = kg >> 3, t = kg & 7;
      const float* ch = Inb + (size_t)c * HW;
      float v[4];
      if (vertical) {
        const int r = y + t - 3;
        if (r >= 0 && r <= 256) {
          const int rr = (r == 256) ? 254 : r;
          float4 f = *(const float4*)&ch[rr * 256 + x0 + bn4];
          v[0] = f.x; v[1] = f.y; v[2] = f.z; v[3] = f.w;
        } else {
          v[0] = v[1] = v[2] = v[3] = 0.f;
        }
      } else {
        const float* row = ch + y * 256;
        const int cbase = x0 + bn4 + t - 3;
#pragma unroll
        for (int ii = 0; ii < 4; ii++) {
          const int cc = cbase + ii;
          v[ii] = (cc >= 0 && cc <= 256) ? row[(cc == 256) ? 254 : cc] : 0.f;
        }
      }
      Bs[bk][bn4 + 0] = v[0]; Bs[bk][bn4 + 1] = v[1];
      Bs[bk][bn4 + 2] = v[2]; Bs[bk][bn4 + 3] = v[3];
    }
    __syncthreads();
#pragma unroll
    for (int k = 0; k < 16; k++) {
      float4 av = *(const float4*)&As[k][ty * 4];
      float4 bv = *(const float4*)&Bs[k][tx * 4];
      float aa[4] = {av.x, av.y, av.z, av.w};
      float bb[4] = {bv.x, bv.y, bv.z, bv.w};
#pragma unroll
      for (int i = 0; i < 4; i++)
#pragma unroll
        for (int j = 0; j < 4; j++) acc[i][j] += aa[i] * bb[j];
    }
    __syncthreads();
  }
#pragma unroll
  for (int i = 0; i < 4; i++) {
    const int m = m0 + ty * 4 + i;
    const float bv = bias[m];
#pragma unroll
    for (int j = 0; j < 4; j++) {
      const int p = p0 + tx * 4 + j;
      float val = acc[i][j] + bv;
      if (accumulate) val += Yb[m * HW + p];
      Yb[m * HW + p] = val;
    }
  }
}

// ---------------------------------------------------------------------------
// Depthwise 8x8 conv (reflect-appended 256->254, zero outside) + BN (eval)
// ---------------------------------------------------------------------------
__global__ void k_dwbn(const float* __restrict__ In, const float* __restrict__ w_dw,
                       const float* __restrict__ gamma, const float* __restrict__ beta,
                       const float* __restrict__ mean, const float* __restrict__ var,
                       float* __restrict__ Out) {
  const int x = blockIdx.x * 32 + threadIdx.x;
  const int y = blockIdx.y * 8 + threadIdx.y;
  const int bc = blockIdx.z;
  const int c = bc & 255;
  const float* in = In + (size_t)bc * HW;
  const float* wdc = w_dw + c * 64;
  float acc = 0.f;
#pragma unroll
  for (int ty2 = 0; ty2 < 8; ty2++) {
    const int r = y + ty2 - 3;
    if (r < 0 || r > 256) continue;
    const int rr = (r == 256) ? 254 : r;
    const float* row = in + rr * 256;
#pragma unroll
    for (int tx2 = 0; tx2 < 8; tx2++) {
      const int cc = x + tx2 - 3;
      if (cc < 0 || cc > 256) continue;
      acc += wdc[ty2 * 8 + tx2] * row[(cc == 256) ? 254 : cc];
    }
  }
  const float sc = gamma[c] / sqrtf(var[c] + 1e-5f);
  Out[(size_t)bc * HW + y * 256 + x] = (acc - mean[c]) * sc + beta[c];
}

// ---------------------------------------------------------------------------
extern "C" void kernel_launch(void* const* d_in, const int* in_sizes, int n_in,
                              void* d_out, int out_size) {
  const float* x         = (const float*)d_in[0];
  const float* w_qkv     = (const float*)d_in[1];
  const float* rel_table = (const float*)d_in[2];
  const float* w_attnx   = (const float*)d_in[3];
  const float* b_attnx   = (const float*)d_in[4];
  const float* w_attny   = (const float*)d_in[5];
  const float* b_attny   = (const float*)d_in[6];
  const float* w_dw      = (const float*)d_in[7];
  const float* bn_gamma  = (const float*)d_in[8];
  const float* bn_beta   = (const float*)d_in[9];
  const float* bn_mean   = (const float*)d_in[10];
  const float* bn_var    = (const float*)d_in[11];
  const float* w_proj    = (const float*)d_in[12];
  float* out = (float*)d_out;

  float *qkvp, *op, *xyp, *bnp;
  cudaGetSymbolAddress((void**)&qkvp, g_qkv);
  cudaGetSymbolAddress((void**)&op,   g_o);
  cudaGetSymbolAddress((void**)&xyp,  g_xy);
  cudaGetSymbolAddress((void**)&bnp,  g_bn);

  // 1) qkv 1x1:  [768,256] @ [256, 65536] per batch
  k_gemm1x1<<<dim3(12, 1024, 2), 256>>>(w_qkv, x, qkvp, 3 * C);
  // 2) window attention
  k_attn<<<dim3(2048, 16), 64>>>(qkvp, rel_table, op);
  // 3) attn-x conv (vertical taps), then attn-y conv (horizontal, accumulate)
  k_convline<<<dim3(4, 1024, 2), 256>>>(w_attnx, b_attnx, op, xyp, 1, 0);
  k_convline<<<dim3(4, 1024, 2), 256>>>(w_attny, b_attny, op, xyp, 0, 1);
  // 4) depthwise 8x8 + BN
  k_dwbn<<<dim3(8, 32, BATCH * C), dim3(32, 8)>>>(xyp, w_dw, bn_gamma, bn_beta,
                                                  bn_mean, bn_var, bnp);
  // 5) final 1x1 projection -> d_out
  k_gemm1x1<<<dim3(4, 1024, 2), 256>>>(w_proj, bnp, out, C);
}

// round 14
// speedup vs baseline: 1.0404x; 1.0404x over previous
#include <cuda_runtime.h>
#include <math.h>

#define BATCH 2
#define C 256
#define HW 65536
#define NH 16
#define DH 16

typedef unsigned long long u64;

__device__ __forceinline__ u64 ffma2(u64 a, u64 b, u64 c) {
  u64 d;
  asm("fma.rn.f32x2 %0, %1, %2, %3;" : "=l"(d) : "l"(a), "l"(b), "l"(c));
  return d;
}
__device__ __forceinline__ u64 dup2(float v) {
  u64 d;
  asm("mov.b64 %0, {%1, %1};" : "=l"(d) : "r"(__float_as_uint(v)));
  return d;
}

// Scratch (device globals — no allocation allowed)
__device__ float g_qkv[(size_t)BATCH * 3 * C * HW]; // 402 MB
__device__ float g_o  [(size_t)BATCH * C * HW];     // 134 MB
__device__ float g_xy [(size_t)BATCH * C * HW];     // 134 MB
__device__ float g_bn [(size_t)BATCH * C * HW];     // 134 MB

// ---------------------------------------------------------------------------
// Packed-f32x2 SGEMM: Y[b][m][p] = sum_k A[m][k] * B[k][p] (+bias)
// Tile 128(M) x 128(N) x 16(K), 256 threads, 8x8 micro-tile as 8x4 f32x2.
// MODE 0: B = X (plain channels, K=256)
// MODE 1: fused line-conv im2col, K=4096:
//   kg<2048:  (c,t)=vertical taps of w_attnx (rows shifted, reflect@256->254)
//   kg>=2048: horizontal taps of w_attny (cols shifted, reflect@256->254)
// ---------------------------------------------------------------------------
template<int MODE>
__global__ __launch_bounds__(256, 2) void k_gemm(
    const float* __restrict__ A0, const float* __restrict__ A1,
    const float* __restrict__ bias0, const float* __restrict__ bias1,
    const float* __restrict__ X, float* __restrict__ Y, int OC) {
  constexpr int K = (MODE == 1) ? 4096 : 256;
  __shared__ float Asd[16][256];   // A duplicated: Asd[k][2m]=Asd[k][2m+1]=A[m][k]
  __shared__ float Bs[16][128];
  const int b = blockIdx.z;
  const float* Xb = X + (size_t)b * C * HW;
  float* Yb = Y + (size_t)b * OC * HW;
  const int m0 = blockIdx.x * 128;
  const int p0 = blockIdx.y * 128;   // 128 pixels, within one image row
  const int y = p0 >> 8;
  const int x0 = p0 & 255;
  const int tid = threadIdx.x;
  const int tx = tid & 15, ty = tid >> 4;
  const int am = tid >> 1, aq = (tid & 1) * 8;   // A loader: row, k-offset
  const int bk = tid >> 4, bn = (tid & 15) * 8;  // B loader

  u64 acc[8][4];
#pragma unroll
  for (int i = 0; i < 8; i++)
#pragma unroll
    for (int j = 0; j < 4; j++) acc[i][j] = 0ull;

  for (int k0 = 0; k0 < K; k0 += 16) {
    // ---- A tile (store pre-duplicated pairs) ----
    {
      const float* src;
      if (MODE == 1) {
        const int kg = k0 + aq;
        src = (kg < 2048) ? A0 + (size_t)(m0 + am) * 2048 + kg
                          : A1 + (size_t)(m0 + am) * 2048 + (kg - 2048);
      } else {
        src = A0 + (size_t)(m0 + am) * K + k0 + aq;
      }
      float4 v0 = *(const float4*)src;
      float4 v1 = *(const float4*)(src + 4);
      *(u64*)&Asd[aq + 0][2 * am] = dup2(v0.x);
      *(u64*)&Asd[aq + 1][2 * am] = dup2(v0.y);
      *(u64*)&Asd[aq + 2][2 * am] = dup2(v0.z);
      *(u64*)&Asd[aq + 3][2 * am] = dup2(v0.w);
      *(u64*)&Asd[aq + 4][2 * am] = dup2(v1.x);
      *(u64*)&Asd[aq + 5][2 * am] = dup2(v1.y);
      *(u64*)&Asd[aq + 6][2 * am] = dup2(v1.z);
      *(u64*)&Asd[aq + 7][2 * am] = dup2(v1.w);
    }
    // ---- B tile ----
    if (MODE == 0) {
      const float* src = Xb + (size_t)(k0 + bk) * HW + p0 + bn;
      *(float4*)&Bs[bk][bn]     = *(const float4*)src;
      *(float4*)&Bs[bk][bn + 4] = *(const float4*)(src + 4);
    } else {
      const int kg = k0 + bk;
      const int part = kg >> 11;
      const int kk = kg & 2047;
      const int c = kk >> 3, t = kk & 7;
      const float* ch = Xb + (size_t)c * HW;
      float v[8];
      if (part == 0) {  // vertical taps
        const int r = y + t - 3;
        if (r >= 0 && r <= 256) {
          const int rr = (r == 256) ? 254 : r;
          float4 f0 = *(const float4*)&ch[rr * 256 + x0 + bn];
          float4 f1 = *(const float4*)&ch[rr * 256 + x0 + bn + 4];
          v[0] = f0.x; v[1] = f0.y; v[2] = f0.z; v[3] = f0.w;
          v[4] = f1.x; v[5] = f1.y; v[6] = f1.z; v[7] = f1.w;
        } else {
#pragma unroll
          for (int ii = 0; ii < 8; ii++) v[ii] = 0.f;
        }
      } else {  // horizontal taps
        const float* row = ch + y * 256;
        const int cbase = x0 + bn + t - 3;
#pragma unroll
        for (int ii = 0; ii < 8; ii++) {
          const int cc = cbase + ii;
          v[ii] = (cc >= 0 && cc <= 256) ? row[(cc == 256) ? 254 : cc] : 0.f;
        }
      }
      Bs[bk][bn + 0] = v[0]; Bs[bk][bn + 1] = v[1];
      Bs[bk][bn + 2] = v[2]; Bs[bk][bn + 3] = v[3];
      Bs[bk][bn + 4] = v[4]; Bs[bk][bn + 5] = v[5];
      Bs[bk][bn + 6] = v[6]; Bs[bk][bn + 7] = v[7];
    }
    __syncthreads();
    // ---- 8x8 micro-tile, packed f32x2 ----
#pragma unroll
    for (int k = 0; k < 16; k++) {
      const ulonglong2* ar2 = (const ulonglong2*)&Asd[k][ty * 16];
      const ulonglong2* br2 = (const ulonglong2*)&Bs[k][tx * 8];
      ulonglong2 q0 = ar2[0], q1 = ar2[1], q2 = ar2[2], q3 = ar2[3];
      ulonglong2 r0 = br2[0], r1 = br2[1];
      u64 ap[8] = {q0.x, q0.y, q1.x, q1.y, q2.x, q2.y, q3.x, q3.y};
      u64 bp[4] = {r0.x, r0.y, r1.x, r1.y};
#pragma unroll
      for (int i = 0; i < 8; i++)
#pragma unroll
        for (int j = 0; j < 4; j++) acc[i][j] = ffma2(ap[i], bp[j], acc[i][j]);
    }
    __syncthreads();
  }
  // ---- epilogue ----
#pragma unroll
  for (int i = 0; i < 8; i++) {
    const int m = m0 + ty * 8 + i;
    float bv = 0.f;
    if (MODE == 1) bv = bias0[m] + bias1[m];
    float o[8];
#pragma unroll
    for (int j = 0; j < 4; j++) {
      o[2 * j + 0] = __uint_as_float((unsigned)(acc[i][j] & 0xffffffffull)) + bv;
      o[2 * j + 1] = __uint_as_float((unsigned)(acc[i][j] >> 32)) + bv;
    }
    *(float4*)&Yb[(size_t)m * HW + p0 + tx * 8]     = make_float4(o[0], o[1], o[2], o[3]);
    *(float4*)&Yb[(size_t)m * HW + p0 + tx * 8 + 4] = make_float4(o[4], o[5], o[6], o[7]);
  }
}

// ---------------------------------------------------------------------------
// Window attention: one block per (window, head), 64 threads = 64 tokens.
// ---------------------------------------------------------------------------
__global__ __launch_bounds__(64) void k_attn(
    const float* __restrict__ qkv, const float* __restrict__ rel_table,
    float* __restrict__ o) {
  const int n = blockIdx.x;
  const int h = blockIdx.y;
  const int i = threadIdx.x;
  __shared__ float ks[64][17];
  __shared__ float vs[64][17];
  __shared__ float rt[225];
  const int b = n >> 10;
  const int rem = n & 1023;
  const int hh = rem >> 5, ww = rem & 31;
  const int yy = i >> 3, xx = i & 7;
  const int py = hh * 8 + yy, px = ww * 8 + xx;
  const size_t base = ((size_t)b * 3 * C + h * DH) * HW + py * 256 + px;
  const float scale = 0.25f;
  float q[16];
#pragma unroll
  for (int dc = 0; dc < 16; dc++) q[dc] = qkv[base + (size_t)dc * HW] * scale;
#pragma unroll
  for (int dc = 0; dc < 16; dc++) ks[i][dc] = qkv[base + (size_t)(C + dc) * HW];
#pragma unroll
  for (int dc = 0; dc < 16; dc++) vs[i][dc] = qkv[base + (size_t)(2 * C + dc) * HW];
  for (int t = i; t < 225; t += 64) rt[t] = rel_table[t * NH + h];
  __syncthreads();

  float p[64];
  float mx = -1e30f;
#pragma unroll
  for (int j = 0; j < 64; j++) {
    const int yj = j >> 3, xj = j & 7;
    float s = 0.f;
#pragma unroll
    for (int dc = 0; dc < 16; dc++) s += q[dc] * ks[j][dc];
    s += rt[(yy - yj + 7) * 15 + (xx - xj + 7)];
    p[j] = s;
    mx = fmaxf(mx, s);
  }
  float sum = 0.f;
#pragma unroll
  for (int j = 0; j < 64; j++) { p[j] = __expf(p[j] - mx); sum += p[j]; }
  const float inv = 1.f / sum;
  const size_t obase = ((size_t)b * C + h * DH) * HW + py * 256 + px;
#pragma unroll
  for (int dc = 0; dc < 16; dc++) {
    float a = 0.f;
#pragma unroll
    for (int j = 0; j < 64; j++) a += p[j] * vs[j][dc];
    o[obase + (size_t)dc * HW] = a * inv;
  }
}

// ---------------------------------------------------------------------------
// Depthwise 8x8 conv (reflect-appended 256->254, zero outside) + BN (eval)
// ---------------------------------------------------------------------------
__global__ void k_dwbn(const float* __restrict__ In, const float* __restrict__ w_dw,
                       const float* __restrict__ gamma, const float* __restrict__ beta,
                       const float* __restrict__ mean, const float* __restrict__ var,
                       float* __restrict__ Out) {
  const int x = blockIdx.x * 32 + threadIdx.x;
  const int y = blockIdx.y * 8 + threadIdx.y;
  const int bc = blockIdx.z;
  const int c = bc & 255;
  const float* in = In + (size_t)bc * HW;
  const float* wdc = w_dw + c * 64;
  float acc = 0.f;
#pragma unroll
  for (int ty2 = 0; ty2 < 8; ty2++) {
    const int r = y + ty2 - 3;
    if (r < 0 || r > 256) continue;
    const int rr = (r == 256) ? 254 : r;
    const float* row = in + rr * 256;
#pragma unroll
    for (int tx2 = 0; tx2 < 8; tx2++) {
      const int cc = x + tx2 - 3;
      if (cc < 0 || cc > 256) continue;
      acc += wdc[ty2 * 8 + tx2] * row[(cc == 256) ? 254 : cc];
    }
  }
  const float sc = gamma[c] / sqrtf(var[c] + 1e-5f);
  Out[(size_t)bc * HW + y * 256 + x] = (acc - mean[c]) * sc + beta[c];
}

// ---------------------------------------------------------------------------
extern "C" void kernel_launch(void* const* d_in, const int* in_sizes, int n_in,
                              void* d_out, int out_size) {
  const float* x         = (const float*)d_in[0];
  const float* w_qkv     = (const float*)d_in[1];
  const float* rel_table = (const float*)d_in[2];
  const float* w_attnx   = (const float*)d_in[3];
  const float* b_attnx   = (const float*)d_in[4];
  const float* w_attny   = (const float*)d_in[5];
  const float* b_attny   = (const float*)d_in[6];
  const float* w_dw      = (const float*)d_in[7];
  const float* bn_gamma  = (const float*)d_in[8];
  const float* bn_beta   = (const float*)d_in[9];
  const float* bn_mean   = (const float*)d_in[10];
  const float* bn_var    = (const float*)d_in[11];
  const float* w_proj    = (const float*)d_in[12];
  float* out = (float*)d_out;

  float *qkvp, *op, *xyp, *bnp;
  cudaGetSymbolAddress((void**)&qkvp, g_qkv);
  cudaGetSymbolAddress((void**)&op,   g_o);
  cudaGetSymbolAddress((void**)&xyp,  g_xy);
  cudaGetSymbolAddress((void**)&bnp,  g_bn);

  // 1) qkv 1x1: [768,256] @ [256,65536] per batch
  k_gemm<0><<<dim3(6, 512, 2), 256>>>(w_qkv, nullptr, nullptr, nullptr, x, qkvp, 3 * C);
  // 2) window attention
  k_attn<<<dim3(2048, 16), 64>>>(qkvp, rel_table, op);
  // 3) fused attn-x + attn-y line convs, K=4096
  k_gemm<1><<<dim3(2, 512, 2), 256>>>(w_attnx, w_attny, b_attnx, b_attny, op, xyp, C);
  // 4) depthwise 8x8 + BN
  k_dwbn<<<dim3(8, 32, BATCH * C), dim3(32, 8)>>>(xyp, w_dw, bn_gamma, bn_beta,
                                                  bn_mean, bn_var, bnp);
  // 5) final 1x1 projection -> d_out
  k_gemm<0><<<dim3(2, 512, 2), 256>>>(w_proj, nullptr, nullptr, nullptr, bnp, out, C);
}